// round 1
// baseline (speedup 1.0000x reference)
#include <cuda_runtime.h>
#include <math.h>

// Problem constants
#define B   128
#define P   196        // 14*14
#define E   2048
#define AA  512        // attention dim
#define EMB 512
#define D   512
#define V   10000
#define LCD 128        // length-class dim
#define TCAP 26
#define T   25
#define XDIM (EMB + E + LCD)   // 2688
#define G4  (4*D)              // 2048

// Output layout (tuple flattened, cast to f32):
// predictions (B,T,V), caps (B,TCAP), dec_len (B,), alphas (B,T,P), sort_ind (B,)
#define OFF_PRED   ((size_t)0)
#define OFF_CAPS   ((size_t)B*T*V)                       // 32,000,000
#define OFF_DECLEN (OFF_CAPS + (size_t)B*TCAP)           // +3328
#define OFF_ALPHAS (OFF_DECLEN + (size_t)B)              // +128
#define OFF_SORT   (OFF_ALPHAS + (size_t)B*T*P)          // +627,200

// ------------------- scratch (static device memory; no allocation) -------------------
__device__ float g_enc_s[(size_t)B*P*E];   // sorted encoder output, ~205MB
__device__ float g_att1[(size_t)B*P*AA];   // enc @ W_enc_att, ~51MB
__device__ float g_mean[B*E];
__device__ float g_h[B*D];
__device__ float g_c[B*D];
__device__ float g_hnew[B*D];
__device__ float g_att2[B*AA];
__device__ float g_alpha[B*P];
__device__ float g_awe[B*E];
__device__ float g_gate[B*E];
__device__ float g_x[B*XDIM];
__device__ float g_gates[B*G4];
__device__ float g_style[B*LCD];
__device__ int   g_sort[B];
__device__ int   g_declen[B];
__device__ float g_maskf[B];

// ------------------- sort + small outputs -------------------
__global__ void k_sort(const int* __restrict__ caps_in,
                       const int* __restrict__ cap_len,
                       const int* __restrict__ length_class,
                       const float* __restrict__ lc_table,
                       float* __restrict__ out)
{
    __shared__ int cls[B];
    int i = threadIdx.x;
    cls[i] = cap_len[i];   // caption_lengths is (B,1)
    __syncthreads();
    int my = cls[i];
    int rank = 0;
    for (int j = 0; j < B; j++) {
        int cj = cls[j];
        if (cj > my || (cj == my && j < i)) rank++;
    }
    g_sort[rank] = i;      // stable descending argsort
    __syncthreads();
    int si = g_sort[i];
    int dl = cls[si] - 1;
    g_declen[i] = dl;
    out[OFF_DECLEN + i] = (float)dl;
    out[OFF_SORT + i]   = (float)si;
    for (int tt = 0; tt < TCAP; tt++)
        out[OFF_CAPS + (size_t)i*TCAP + tt] = (float)caps_in[si*TCAP + tt];
    int lcidx = length_class[si];
    for (int j = 0; j < LCD; j++)
        g_style[i*LCD + j] = lc_table[lcidx*LCD + j];
}

// ------------------- gather sorted enc -------------------
__global__ void k_gather(const float* __restrict__ enc)
{
    size_t i  = (size_t)blockIdx.x * blockDim.x + threadIdx.x;  // float4 index
    size_t e4 = i * 4;
    int b      = (int)(e4 / ((size_t)P*E));
    size_t rem = e4 % ((size_t)P*E);
    const float4* src = (const float4*)(enc + (size_t)g_sort[b]*P*E + rem);
    *(float4*)(g_enc_s + e4) = *src;
}

// ------------------- mean over pixels -------------------
__global__ void k_mean()
{
    int b = blockIdx.y;
    int e = blockIdx.x * 256 + threadIdx.x;
    const float* base = g_enc_s + (size_t)b*P*E + e;
    float s = 0.f;
    #pragma unroll 4
    for (int p = 0; p < P; p++) s += base[(size_t)p*E];
    g_mean[b*E + e] = s * (1.0f / (float)P);
}

// ------------------- generic tiled GEMM: C = act(A@W + bias [+ C]) * row_scale ---------
// A: M x K row-major (lda), W: K x N row-major (ldw), C: M x N (ldc)
// act: 0 none, 1 sigmoid. acc: 1 -> add previous C. row_scale: per-row multiplier or null.
#define BM 64
#define BN 64
#define BK 16

__global__ __launch_bounds__(256)
void k_gemm(const float* __restrict__ Am, int lda,
            const float* __restrict__ W,  int ldw,
            const float* __restrict__ bias,
            float* __restrict__ C, int ldc,
            const float* __restrict__ row_scale,
            int M, int N, int K, int act, int acc)
{
    __shared__ float As[BK][BM];
    __shared__ float Ws[BK][BN];
    int tid = threadIdx.x;
    int tx = tid & 15, ty = tid >> 4;
    int bm = blockIdx.y * BM, bn = blockIdx.x * BN;

    int a_m = tid >> 2;          // 0..63
    int a_k = (tid & 3) * 4;     // 0,4,8,12
    int w_k = tid >> 4;          // 0..15
    int w_n = (tid & 15) * 4;    // 0..60

    float accr[4][4];
    #pragma unroll
    for (int i = 0; i < 4; i++)
        #pragma unroll
        for (int j = 0; j < 4; j++) accr[i][j] = 0.f;

    for (int k0 = 0; k0 < K; k0 += BK) {
        // load A tile (K assumed multiple of 16)
        {
            int gm = bm + a_m;
            float4 v = make_float4(0.f, 0.f, 0.f, 0.f);
            if (gm < M) v = *(const float4*)(Am + (size_t)gm * lda + k0 + a_k);
            As[a_k+0][a_m] = v.x; As[a_k+1][a_m] = v.y;
            As[a_k+2][a_m] = v.z; As[a_k+3][a_m] = v.w;
        }
        // load W tile
        {
            int gn = bn + w_n;
            float4 v = make_float4(0.f, 0.f, 0.f, 0.f);
            if (gn < N) v = *(const float4*)(W + (size_t)(k0 + w_k) * ldw + gn);
            *(float4*)&Ws[w_k][w_n] = v;
        }
        __syncthreads();
        #pragma unroll
        for (int kk = 0; kk < BK; kk++) {
            float4 av = *(const float4*)&As[kk][ty*4];
            float4 bv = *(const float4*)&Ws[kk][tx*4];
            float a0 = av.x, a1 = av.y, a2 = av.z, a3 = av.w;
            float b0 = bv.x, b1 = bv.y, b2 = bv.z, b3 = bv.w;
            accr[0][0] += a0*b0; accr[0][1] += a0*b1; accr[0][2] += a0*b2; accr[0][3] += a0*b3;
            accr[1][0] += a1*b0; accr[1][1] += a1*b1; accr[1][2] += a1*b2; accr[1][3] += a1*b3;
            accr[2][0] += a2*b0; accr[2][1] += a2*b1; accr[2][2] += a2*b2; accr[2][3] += a2*b3;
            accr[3][0] += a3*b0; accr[3][1] += a3*b1; accr[3][2] += a3*b2; accr[3][3] += a3*b3;
        }
        __syncthreads();
    }

    #pragma unroll
    for (int i = 0; i < 4; i++) {
        int gm = bm + ty*4 + i;
        if (gm >= M) continue;
        float rs = row_scale ? row_scale[gm] : 1.f;
        #pragma unroll
        for (int j = 0; j < 4; j++) {
            int gn = bn + tx*4 + j;
            if (gn >= N) continue;
            float v = accr[i][j] + (bias ? bias[gn] : 0.f);
            size_t ci = (size_t)gm * ldc + gn;
            if (acc) v += C[ci];
            if (act == 1) v = 1.f / (1.f + expf(-v));
            C[ci] = v * rs;
        }
    }
}

// ------------------- attention scores + softmax -------------------
__global__ void k_escore(const float* __restrict__ w_full,
                         const float* __restrict__ b_full,
                         float* __restrict__ out, int t)
{
    int b = blockIdx.x;
    __shared__ float att2s[AA], ws[AA], es[P], red[256];
    int tid = threadIdx.x;
    for (int j = tid; j < AA; j += 256) {
        att2s[j] = g_att2[b*AA + j];
        ws[j]    = w_full[j];
    }
    __syncthreads();
    int warp = tid >> 5, lane = tid & 31;
    float bf = *b_full;
    for (int p = warp; p < P; p += 8) {
        const float* row = g_att1 + ((size_t)b*P + p)*AA;
        float acc = 0.f;
        #pragma unroll 4
        for (int a = lane; a < AA; a += 32) {
            float v = row[a] + att2s[a];
            v = fmaxf(v, 0.f);
            acc += v * ws[a];
        }
        #pragma unroll
        for (int o = 16; o > 0; o >>= 1) acc += __shfl_down_sync(0xffffffffu, acc, o);
        if (lane == 0) es[p] = acc + bf;
    }
    __syncthreads();
    // softmax over P=196
    float m = -1e30f;
    for (int p = tid; p < P; p += 256) m = fmaxf(m, es[p]);
    red[tid] = m; __syncthreads();
    for (int s = 128; s > 0; s >>= 1) { if (tid < s) red[tid] = fmaxf(red[tid], red[tid+s]); __syncthreads(); }
    float mx = red[0]; __syncthreads();
    float sum = 0.f;
    for (int p = tid; p < P; p += 256) sum += expf(es[p] - mx);
    red[tid] = sum; __syncthreads();
    for (int s = 128; s > 0; s >>= 1) { if (tid < s) red[tid] += red[tid+s]; __syncthreads(); }
    float inv = 1.f / red[0];
    float maskv = (t < g_declen[b]) ? 1.f : 0.f;
    if (tid == 0) g_maskf[b] = maskv;
    for (int p = tid; p < P; p += 256) {
        float al = expf(es[p] - mx) * inv;
        g_alpha[b*P + p] = al;
        out[OFF_ALPHAS + ((size_t)b*T + t)*P + p] = al * maskv;
    }
}

// ------------------- attention-weighted encoding -------------------
__global__ void k_awe()
{
    int b  = blockIdx.y;
    int e0 = blockIdx.x * 512;
    __shared__ float als[P];
    int tid = threadIdx.x;  // 256
    if (tid < P) als[tid] = g_alpha[b*P + tid];
    __syncthreads();
    float acc0 = 0.f, acc1 = 0.f;
    const float* base = g_enc_s + (size_t)b*P*E + e0 + tid;
    #pragma unroll 2
    for (int p = 0; p < P; p++) {
        float al = als[p];
        acc0 += base[(size_t)p*E]       * al;
        acc1 += base[(size_t)p*E + 256] * al;
    }
    g_awe[b*E + e0 + tid]       = acc0;
    g_awe[b*E + e0 + tid + 256] = acc1;
}

// ------------------- build LSTM input x = [emb_t, style, gate*awe] -------------------
__global__ void k_buildx(const float* __restrict__ emb_table,
                         const int* __restrict__ caps_in, int t)
{
    int idx = blockIdx.x * 256 + threadIdx.x;
    if (idx >= B * XDIM) return;
    int b = idx / XDIM, col = idx % XDIM;
    float v;
    if (col < EMB) {
        int cap = caps_in[g_sort[b]*TCAP + t];
        v = emb_table[(size_t)cap*EMB + col];
    } else if (col < EMB + LCD) {
        v = g_style[b*LCD + (col - EMB)];
    } else {
        int j = col - (EMB + LCD);
        v = g_gate[b*E + j] * g_awe[b*E + j];
    }
    g_x[idx] = v;
}

// ------------------- LSTM pointwise -------------------
__global__ void k_lstm(int t)
{
    int idx = blockIdx.x * 256 + threadIdx.x;  // B*D
    int b = idx / D, j = idx % D;
    const float* gr = g_gates + (size_t)b*G4;
    float ig = gr[j], fg = gr[D + j], gg = gr[2*D + j], og = gr[3*D + j];
    float si = 1.f / (1.f + expf(-ig));
    float sf = 1.f / (1.f + expf(-fg));
    float so = 1.f / (1.f + expf(-og));
    float cn = sf * g_c[idx] + si * tanhf(gg);
    float hn = so * tanhf(cn);
    g_hnew[idx] = hn;
    if (t < g_declen[b]) { g_h[idx] = hn; g_c[idx] = cn; }
}

// ------------------- host launcher -------------------
extern "C" void kernel_launch(void* const* d_in, const int* in_sizes, int n_in,
                              void* d_out, int out_size)
{
    const float* encoder_out  = (const float*)d_in[0];
    const int*   caps_in      = (const int*)  d_in[1];
    const int*   cap_len      = (const int*)  d_in[2];
    const int*   length_class = (const int*)  d_in[3];
    const float* W_enc_att    = (const float*)d_in[4];
    const float* b_enc_att    = (const float*)d_in[5];
    const float* W_dec_att    = (const float*)d_in[6];
    const float* b_dec_att    = (const float*)d_in[7];
    const float* w_full_att   = (const float*)d_in[8];
    const float* b_full_att   = (const float*)d_in[9];
    const float* W_init_h     = (const float*)d_in[10];
    const float* b_init_h     = (const float*)d_in[11];
    const float* W_init_c     = (const float*)d_in[12];
    const float* b_init_c     = (const float*)d_in[13];
    const float* W_fbeta      = (const float*)d_in[14];
    const float* b_fbeta      = (const float*)d_in[15];
    const float* emb_table    = (const float*)d_in[16];
    const float* lc_table     = (const float*)d_in[17];
    const float* W_fc         = (const float*)d_in[18];
    const float* b_fc         = (const float*)d_in[19];
    const float* W_ih         = (const float*)d_in[20];
    const float* b_ih         = (const float*)d_in[21];
    const float* W_hh         = (const float*)d_in[22];
    const float* b_hh         = (const float*)d_in[23];
    float* out = (float*)d_out;

    // device-symbol addresses for the generic GEMM
    void* tmp;
    float *p_enc, *p_att1, *p_mean, *p_h, *p_c, *p_hnew, *p_att2, *p_gate, *p_x, *p_gates, *p_mask;
    cudaGetSymbolAddress(&tmp, g_enc_s); p_enc   = (float*)tmp;
    cudaGetSymbolAddress(&tmp, g_att1);  p_att1  = (float*)tmp;
    cudaGetSymbolAddress(&tmp, g_mean);  p_mean  = (float*)tmp;
    cudaGetSymbolAddress(&tmp, g_h);     p_h     = (float*)tmp;
    cudaGetSymbolAddress(&tmp, g_c);     p_c     = (float*)tmp;
    cudaGetSymbolAddress(&tmp, g_hnew);  p_hnew  = (float*)tmp;
    cudaGetSymbolAddress(&tmp, g_att2);  p_att2  = (float*)tmp;
    cudaGetSymbolAddress(&tmp, g_gate);  p_gate  = (float*)tmp;
    cudaGetSymbolAddress(&tmp, g_x);     p_x     = (float*)tmp;
    cudaGetSymbolAddress(&tmp, g_gates); p_gates = (float*)tmp;
    cudaGetSymbolAddress(&tmp, g_maskf); p_mask  = (float*)tmp;

    // setup
    k_sort<<<1, B>>>(caps_in, cap_len, length_class, lc_table, out);
    k_gather<<<(B*P*E/4 + 255)/256, 256>>>(encoder_out);
    k_mean<<<dim3(E/256, B), 256>>>();

    // h0 = mean @ W_init_h + b ; c0 likewise   (M=128, N=512, K=2048)
    k_gemm<<<dim3(D/BN, B/BM), 256>>>(p_mean, E, W_init_h, D, b_init_h, p_h, D, nullptr, B, D, E, 0, 0);
    k_gemm<<<dim3(D/BN, B/BM), 256>>>(p_mean, E, W_init_c, D, b_init_c, p_c, D, nullptr, B, D, E, 0, 0);

    // att1 = enc_s @ W_enc_att + b   (M=25088, N=512, K=2048)
    k_gemm<<<dim3(AA/BN, (B*P)/BM), 256>>>(p_enc, E, W_enc_att, AA, b_enc_att, p_att1, AA, nullptr, B*P, AA, E, 0, 0);

    for (int t = 0; t < T; t++) {
        // att2 = h @ W_dec_att + b   (128 x 512 x 512)
        k_gemm<<<dim3(AA/BN, B/BM), 256>>>(p_h, D, W_dec_att, AA, b_dec_att, p_att2, AA, nullptr, B, AA, D, 0, 0);
        // scores + softmax (writes alpha + masked alphas output)
        k_escore<<<B, 256>>>(w_full_att, b_full_att, out, t);
        // awe = alpha-weighted sum of enc
        k_awe<<<dim3(E/512, B), 256>>>();
        // gate = sigmoid(h @ W_fbeta + b)   (128 x 2048 x 512)
        k_gemm<<<dim3(E/BN, B/BM), 256>>>(p_h, D, W_fbeta, E, b_fbeta, p_gate, E, nullptr, B, E, D, 1, 0);
        // x = [emb_t, style, gate*awe]
        k_buildx<<<(B*XDIM + 255)/256, 256>>>(emb_table, caps_in, t);
        // gates = x @ W_ih + b_ih + h @ W_hh + b_hh
        k_gemm<<<dim3(G4/BN, B/BM), 256>>>(p_x, XDIM, W_ih, G4, b_ih, p_gates, G4, nullptr, B, G4, XDIM, 0, 0);
        k_gemm<<<dim3(G4/BN, B/BM), 256>>>(p_h, D, W_hh, G4, b_hh, p_gates, G4, nullptr, B, G4, D, 0, 1);
        // LSTM cell + masked carry update
        k_lstm<<<(B*D)/256, 256>>>(t);
        // preds (masked) straight into output: C base = out + t*V, ldc = T*V
        k_gemm<<<dim3((V + BN - 1)/BN, B/BM), 256>>>(p_hnew, D, W_fc, V, b_fc,
                                                     out + (size_t)t*V, T*V, p_mask,
                                                     B, V, D, 0, 0);
    }
}

// round 2
// speedup vs baseline: 1.8267x; 1.8267x over previous
#include <cuda_runtime.h>
#include <math.h>

// Problem constants
#define B   128
#define P   196        // 14*14
#define E   2048
#define AA  512        // attention dim
#define EMB 512
#define D   512
#define V   10000
#define LCD 128        // length-class dim
#define TCAP 26
#define T   25
#define XDIM (EMB + E + LCD)   // 2688
#define G4  (4*D)              // 2048
#define NCAT (AA + E + G4)     // 4608 : [W_dec_att | W_fbeta | W_hh]

// Output layout (tuple flattened, cast to f32):
// predictions (B,T,V), caps (B,TCAP), dec_len (B,), alphas (B,T,P), sort_ind (B,)
#define OFF_PRED   ((size_t)0)
#define OFF_CAPS   ((size_t)B*T*V)
#define OFF_DECLEN (OFF_CAPS + (size_t)B*TCAP)
#define OFF_ALPHAS (OFF_DECLEN + (size_t)B)
#define OFF_SORT   (OFF_ALPHAS + (size_t)B*T*P)

// ------------------- scratch (static device memory) -------------------
__device__ float g_enc_s[(size_t)B*P*E];   // sorted encoder output
__device__ float g_att1[(size_t)B*P*AA];   // enc @ W_enc_att (NO bias)
__device__ float g_Wcat[(size_t)D*NCAT];   // [W_dec_att | W_fbeta | W_hh]
__device__ float g_part[2560000];          // split-K partials (max: preds 2*128*10000)
__device__ float g_mean[B*E];
__device__ float g_h[B*D];
__device__ float g_c[B*D];
__device__ float g_hnew[B*D];
__device__ float g_att2[B*AA];             // includes b_dec_att + b_enc_att
__device__ float g_alpha[B*P];
__device__ float g_awe[B*E];
__device__ float g_gate[B*E];              // sigmoided
__device__ float g_hh[B*G4];               // h @ W_hh + b_hh
__device__ float g_x[B*XDIM];
__device__ float g_style[B*LCD];
__device__ int   g_sort[B];
__device__ int   g_declen[B];
__device__ float g_maskf[B];

// ------------------- sort + small outputs -------------------
__global__ void k_sort(const int* __restrict__ caps_in,
                       const int* __restrict__ cap_len,
                       const int* __restrict__ length_class,
                       const float* __restrict__ lc_table,
                       float* __restrict__ out)
{
    __shared__ int cls[B];
    int i = threadIdx.x;
    cls[i] = cap_len[i];
    __syncthreads();
    int my = cls[i];
    int rank = 0;
    for (int j = 0; j < B; j++) {
        int cj = cls[j];
        if (cj > my || (cj == my && j < i)) rank++;
    }
    g_sort[rank] = i;      // stable descending argsort
    __syncthreads();
    int si = g_sort[i];
    int dl = cls[si] - 1;
    g_declen[i] = dl;
    out[OFF_DECLEN + i] = (float)dl;
    out[OFF_SORT + i]   = (float)si;
    for (int tt = 0; tt < TCAP; tt++)
        out[OFF_CAPS + (size_t)i*TCAP + tt] = (float)caps_in[si*TCAP + tt];
    int lcidx = length_class[si];
    for (int j = 0; j < LCD; j++)
        g_style[i*LCD + j] = lc_table[lcidx*LCD + j];
}

// ------------------- gather sorted enc -------------------
__global__ void k_gather(const float* __restrict__ enc)
{
    size_t i  = (size_t)blockIdx.x * blockDim.x + threadIdx.x;  // float4 index
    size_t e4 = i * 4;
    int b      = (int)(e4 / ((size_t)P*E));
    size_t rem = e4 % ((size_t)P*E);
    const float4* src = (const float4*)(enc + (size_t)g_sort[b]*P*E + rem);
    *(float4*)(g_enc_s + e4) = *src;
}

// ------------------- mean over pixels -------------------
__global__ void k_mean()
{
    int b = blockIdx.y;
    int e = blockIdx.x * 256 + threadIdx.x;
    const float* base = g_enc_s + (size_t)b*P*E + e;
    float s = 0.f;
    #pragma unroll 4
    for (int p = 0; p < P; p++) s += base[(size_t)p*E];
    g_mean[b*E + e] = s * (1.0f / (float)P);
}

// ------------------- concat weights [W_dec_att | W_fbeta | W_hh] ----------
__global__ void k_concatW(const float* __restrict__ Wdec,
                          const float* __restrict__ Wfb,
                          const float* __restrict__ Whh)
{
    int idx = blockIdx.x * 256 + threadIdx.x;   // over D*NCAT
    if (idx >= D * NCAT) return;
    int k = idx / NCAT, n = idx % NCAT;
    float v;
    if (n < AA)            v = Wdec[k*AA + n];
    else if (n < AA + E)   v = Wfb[k*E + (n - AA)];
    else                   v = Whh[k*G4 + (n - AA - E)];
    g_Wcat[idx] = v;
}

// =================== tiled GEMM (M mult of 128): partials, split-K ===================
// part[z][M][N] += A[bm..][kbase..kbase+Kc] @ W[kbase..][bn..]
#define GBM 128
#define GBN 64
#define GBK 16

__global__ __launch_bounds__(256)
void k_gemm128(const float* __restrict__ Am, int lda,
               const float* __restrict__ W,  int ldw,
               float* __restrict__ part,
               int M, int N, int Kc)
{
    __shared__ float As[2][GBK][GBM];
    __shared__ float Ws[2][GBK][GBN];
    int tid = threadIdx.x;
    int bn = blockIdx.x * GBN;
    int bm = blockIdx.y * GBM;
    int kbase = blockIdx.z * Kc;

    // A load: row a_m, k-offset a_k..a_k+7 (two float4)
    int a_m = tid >> 1;
    int a_k = (tid & 1) * 8;
    // W load: row w_k, col w_n (one float4)
    int w_k = tid >> 4;
    int w_n = (tid & 15) * 4;

    // compute layout: 8 rows x 4 cols per thread
    int tx = tid & 15;            // col group
    int ty = tid >> 4;            // row group
    int ty8 = ty * 8, tx4 = tx * 4;

    const float* arow = Am + (size_t)(bm + a_m) * lda + kbase + a_k;
    const float* wptr = W + (size_t)(kbase + w_k) * ldw + bn + w_n;
    bool wok = (bn + w_n) < N;

    float acc[8][4];
    #pragma unroll
    for (int i = 0; i < 8; i++)
        #pragma unroll
        for (int j = 0; j < 4; j++) acc[i][j] = 0.f;

    int iters = Kc / GBK;

    // prologue: tile 0
    {
        float4 a0 = *(const float4*)(arow);
        float4 a1 = *(const float4*)(arow + 4);
        float4 w  = wok ? *(const float4*)(wptr) : make_float4(0,0,0,0);
        As[0][a_k+0][a_m] = a0.x; As[0][a_k+1][a_m] = a0.y;
        As[0][a_k+2][a_m] = a0.z; As[0][a_k+3][a_m] = a0.w;
        As[0][a_k+4][a_m] = a1.x; As[0][a_k+5][a_m] = a1.y;
        As[0][a_k+6][a_m] = a1.z; As[0][a_k+7][a_m] = a1.w;
        *(float4*)&Ws[0][w_k][w_n] = w;
    }
    __syncthreads();

    int buf = 0;
    for (int it = 0; it < iters; it++) {
        float4 pa0, pa1, pw;
        bool has_next = (it + 1 < iters);
        if (has_next) {
            const float* an = arow + (it + 1) * GBK;
            pa0 = *(const float4*)(an);
            pa1 = *(const float4*)(an + 4);
            pw  = wok ? *(const float4*)(wptr + (size_t)(it + 1) * GBK * ldw)
                      : make_float4(0,0,0,0);
        }
        #pragma unroll
        for (int kk = 0; kk < GBK; kk++) {
            float4 a0 = *(const float4*)&As[buf][kk][ty8];
            float4 a1 = *(const float4*)&As[buf][kk][ty8 + 4];
            float4 w  = *(const float4*)&Ws[buf][kk][tx4];
            float av[8] = {a0.x,a0.y,a0.z,a0.w,a1.x,a1.y,a1.z,a1.w};
            float wv[4] = {w.x,w.y,w.z,w.w};
            #pragma unroll
            for (int i = 0; i < 8; i++)
                #pragma unroll
                for (int j = 0; j < 4; j++)
                    acc[i][j] += av[i] * wv[j];
        }
        if (has_next) {
            int nb = buf ^ 1;
            As[nb][a_k+0][a_m] = pa0.x; As[nb][a_k+1][a_m] = pa0.y;
            As[nb][a_k+2][a_m] = pa0.z; As[nb][a_k+3][a_m] = pa0.w;
            As[nb][a_k+4][a_m] = pa1.x; As[nb][a_k+5][a_m] = pa1.y;
            As[nb][a_k+6][a_m] = pa1.z; As[nb][a_k+7][a_m] = pa1.w;
            *(float4*)&Ws[nb][w_k][w_n] = pw;
        }
        __syncthreads();
        buf ^= 1;
    }

    float* pout = part + (size_t)blockIdx.z * M * N;
    #pragma unroll
    for (int i = 0; i < 8; i++) {
        int gm = bm + ty8 + i;
        #pragma unroll
        for (int j = 0; j < 4; j++) {
            int gn = bn + tx4 + j;
            if (gn < N) pout[(size_t)gm * N + gn] = acc[i][j];
        }
    }
}

// ------------------- epilogue: fused h-GEMM (S=4) -------------------
__global__ void k_epi_h(const float* __restrict__ b_dec, const float* __restrict__ b_enc,
                        const float* __restrict__ b_fbeta, const float* __restrict__ b_hh)
{
    int idx = blockIdx.x * 256 + threadIdx.x;   // over B*NCAT
    if (idx >= B * NCAT) return;
    int b = idx / NCAT, n = idx % NCAT;
    float s = g_part[idx] + g_part[(size_t)1*B*NCAT + idx]
            + g_part[(size_t)2*B*NCAT + idx] + g_part[(size_t)3*B*NCAT + idx];
    if (n < AA) {
        g_att2[b*AA + n] = s + b_dec[n] + b_enc[n];
    } else if (n < AA + E) {
        int j = n - AA;
        g_gate[b*E + j] = 1.f / (1.f + expf(-(s + b_fbeta[j])));
    } else {
        int j = n - AA - E;
        g_hh[b*G4 + j] = s + b_hh[j];
    }
}

// ------------------- epilogue: init h / c (S=8, N=512) -------------------
__global__ void k_epi_hc(float* __restrict__ dst, const float* __restrict__ bias)
{
    int idx = blockIdx.x * 256 + threadIdx.x;   // over B*D
    int n = idx % D;
    float s = bias[n];
    #pragma unroll
    for (int z = 0; z < 8; z++) s += g_part[(size_t)z*B*D + idx];
    dst[idx] = s;
}

// ------------------- attention scores + softmax -------------------
__global__ void k_escore(const float* __restrict__ w_full,
                         const float* __restrict__ b_full,
                         float* __restrict__ out, int t)
{
    int b = blockIdx.x;
    __shared__ float att2s[AA], ws[AA], es[P], red[256];
    int tid = threadIdx.x;
    for (int j = tid; j < AA; j += 256) {
        att2s[j] = g_att2[b*AA + j];
        ws[j]    = w_full[j];
    }
    __syncthreads();
    int warp = tid >> 5, lane = tid & 31;
    float bf = *b_full;
    for (int p = warp; p < P; p += 8) {
        const float* row = g_att1 + ((size_t)b*P + p)*AA;
        float acc = 0.f;
        #pragma unroll 4
        for (int a = lane; a < AA; a += 32) {
            float v = row[a] + att2s[a];
            v = fmaxf(v, 0.f);
            acc += v * ws[a];
        }
        #pragma unroll
        for (int o = 16; o > 0; o >>= 1) acc += __shfl_down_sync(0xffffffffu, acc, o);
        if (lane == 0) es[p] = acc + bf;
    }
    __syncthreads();
    float m = -1e30f;
    for (int p = tid; p < P; p += 256) m = fmaxf(m, es[p]);
    red[tid] = m; __syncthreads();
    for (int s = 128; s > 0; s >>= 1) { if (tid < s) red[tid] = fmaxf(red[tid], red[tid+s]); __syncthreads(); }
    float mx = red[0]; __syncthreads();
    float sum = 0.f;
    for (int p = tid; p < P; p += 256) sum += expf(es[p] - mx);
    red[tid] = sum; __syncthreads();
    for (int s = 128; s > 0; s >>= 1) { if (tid < s) red[tid] += red[tid+s]; __syncthreads(); }
    float inv = 1.f / red[0];
    float maskv = (t < g_declen[b]) ? 1.f : 0.f;
    if (tid == 0) g_maskf[b] = maskv;
    for (int p = tid; p < P; p += 256) {
        float al = expf(es[p] - mx) * inv;
        g_alpha[b*P + p] = al;
        out[OFF_ALPHAS + ((size_t)b*T + t)*P + p] = al * maskv;
    }
}

// ------------------- attention-weighted encoding -------------------
__global__ void k_awe()
{
    int b  = blockIdx.y;
    int e0 = blockIdx.x * 512;
    __shared__ float als[P];
    int tid = threadIdx.x;  // 256
    if (tid < P) als[tid] = g_alpha[b*P + tid];
    __syncthreads();
    float acc0 = 0.f, acc1 = 0.f;
    const float* base = g_enc_s + (size_t)b*P*E + e0 + tid;
    #pragma unroll 2
    for (int p = 0; p < P; p++) {
        float al = als[p];
        acc0 += base[(size_t)p*E]       * al;
        acc1 += base[(size_t)p*E + 256] * al;
    }
    g_awe[b*E + e0 + tid]       = acc0;
    g_awe[b*E + e0 + tid + 256] = acc1;
}

// ------------------- build LSTM input x = [emb_t, style, gate*awe] -------------------
__global__ void k_buildx(const float* __restrict__ emb_table,
                         const int* __restrict__ caps_in, int t)
{
    int idx = blockIdx.x * 256 + threadIdx.x;
    if (idx >= B * XDIM) return;
    int b = idx / XDIM, col = idx % XDIM;
    float v;
    if (col < EMB) {
        int cap = caps_in[g_sort[b]*TCAP + t];
        v = emb_table[(size_t)cap*EMB + col];
    } else if (col < EMB + LCD) {
        v = g_style[b*LCD + (col - EMB)];
    } else {
        int j = col - (EMB + LCD);
        v = g_gate[b*E + j] * g_awe[b*E + j];
    }
    g_x[idx] = v;
}

// ------------------- fused W_ih epilogue + LSTM pointwise (S=8) -------------------
__global__ void k_lstm(const float* __restrict__ b_ih, int t)
{
    int idx = blockIdx.x * 256 + threadIdx.x;  // B*D
    int b = idx / D, j = idx % D;
    float gate4[4];
    #pragma unroll
    for (int g = 0; g < 4; g++) {
        int n = g * D + j;
        float s = b_ih[n] + g_hh[b*G4 + n];
        #pragma unroll
        for (int z = 0; z < 8; z++)
            s += g_part[(size_t)z*B*G4 + (size_t)b*G4 + n];
        gate4[g] = s;
    }
    float si = 1.f / (1.f + expf(-gate4[0]));
    float sf = 1.f / (1.f + expf(-gate4[1]));
    float so = 1.f / (1.f + expf(-gate4[3]));
    float cn = sf * g_c[idx] + si * tanhf(gate4[2]);
    float hn = so * tanhf(cn);
    g_hnew[idx] = hn;
    if (t < g_declen[b]) { g_h[idx] = hn; g_c[idx] = cn; }
}

// ------------------- preds epilogue (S=2) -------------------
__global__ void k_epi_preds(const float* __restrict__ b_fc,
                            float* __restrict__ out, int t)
{
    int idx = blockIdx.x * 256 + threadIdx.x;   // over B*V
    if (idx >= B * V) return;
    int b = idx / V, n = idx % V;
    float s = g_part[idx] + g_part[(size_t)B*V + idx] + b_fc[n];
    out[OFF_PRED + (size_t)b*T*V + (size_t)t*V + n] = s * g_maskf[b];
}

// ------------------- host launcher -------------------
extern "C" void kernel_launch(void* const* d_in, const int* in_sizes, int n_in,
                              void* d_out, int out_size)
{
    const float* encoder_out  = (const float*)d_in[0];
    const int*   caps_in      = (const int*)  d_in[1];
    const int*   cap_len      = (const int*)  d_in[2];
    const int*   length_class = (const int*)  d_in[3];
    const float* W_enc_att    = (const float*)d_in[4];
    const float* b_enc_att    = (const float*)d_in[5];
    const float* W_dec_att    = (const float*)d_in[6];
    const float* b_dec_att    = (const float*)d_in[7];
    const float* w_full_att   = (const float*)d_in[8];
    const float* b_full_att   = (const float*)d_in[9];
    const float* W_init_h     = (const float*)d_in[10];
    const float* b_init_h     = (const float*)d_in[11];
    const float* W_init_c     = (const float*)d_in[12];
    const float* b_init_c     = (const float*)d_in[13];
    const float* W_fbeta      = (const float*)d_in[14];
    const float* b_fbeta      = (const float*)d_in[15];
    const float* emb_table    = (const float*)d_in[16];
    const float* lc_table     = (const float*)d_in[17];
    const float* W_fc         = (const float*)d_in[18];
    const float* b_fc         = (const float*)d_in[19];
    const float* W_ih         = (const float*)d_in[20];
    const float* b_ih         = (const float*)d_in[21];
    const float* W_hh         = (const float*)d_in[22];
    const float* b_hh         = (const float*)d_in[23];
    float* out = (float*)d_out;

    void* tmp;
    float *p_enc, *p_att1, *p_mean, *p_h, *p_c, *p_hnew, *p_x, *p_Wcat, *p_part;
    cudaGetSymbolAddress(&tmp, g_enc_s); p_enc  = (float*)tmp;
    cudaGetSymbolAddress(&tmp, g_att1);  p_att1 = (float*)tmp;
    cudaGetSymbolAddress(&tmp, g_mean);  p_mean = (float*)tmp;
    cudaGetSymbolAddress(&tmp, g_h);     p_h    = (float*)tmp;
    cudaGetSymbolAddress(&tmp, g_c);     p_c    = (float*)tmp;
    cudaGetSymbolAddress(&tmp, g_hnew);  p_hnew = (float*)tmp;
    cudaGetSymbolAddress(&tmp, g_x);     p_x    = (float*)tmp;
    cudaGetSymbolAddress(&tmp, g_Wcat);  p_Wcat = (float*)tmp;
    cudaGetSymbolAddress(&tmp, g_part);  p_part = (float*)tmp;

    // ---- setup ----
    k_sort<<<1, B>>>(caps_in, cap_len, length_class, lc_table, out);
    k_gather<<<(B*P*E/4 + 255)/256, 256>>>(encoder_out);
    k_concatW<<<(D*NCAT + 255)/256, 256>>>(W_dec_att, W_fbeta, W_hh);
    k_mean<<<dim3(E/256, B), 256>>>();

    // h0 / c0: M=128, N=512, K=2048, split S=8 (Kc=256)
    k_gemm128<<<dim3(D/GBN, 1, 8), 256>>>(p_mean, E, W_init_h, D, p_part, B, D, 256);
    k_epi_hc<<<(B*D)/256, 256>>>(p_h, b_init_h);
    k_gemm128<<<dim3(D/GBN, 1, 8), 256>>>(p_mean, E, W_init_c, D, p_part, B, D, 256);
    k_epi_hc<<<(B*D)/256, 256>>>(p_c, b_init_c);

    // att1 = enc_s @ W_enc_att   (M=25088, N=512, K=2048, no split, no bias)
    k_gemm128<<<dim3(AA/GBN, (B*P)/GBM, 1), 256>>>(p_enc, E, W_enc_att, AA, p_att1, B*P, AA, E);

    for (int t = 0; t < T; t++) {
        // fused: h @ [W_dec|W_fbeta|W_hh]  (N=4608, K=512, S=4, Kc=128)
        k_gemm128<<<dim3(NCAT/GBN, 1, 4), 256>>>(p_h, D, p_Wcat, NCAT, p_part, B, NCAT, 128);
        k_epi_h<<<(B*NCAT + 255)/256, 256>>>(b_dec_att, b_enc_att, b_fbeta, b_hh);
        // scores + softmax (alpha + masked alphas output)
        k_escore<<<B, 256>>>(w_full_att, b_full_att, out, t);
        // awe = alpha-weighted sum of enc
        k_awe<<<dim3(E/512, B), 256>>>();
        // x = [emb_t, style, gate*awe]
        k_buildx<<<(B*XDIM + 255)/256, 256>>>(emb_table, caps_in, t);
        // x @ W_ih  (N=2048, K=2688, S=8, Kc=336)
        k_gemm128<<<dim3(G4/GBN, 1, 8), 256>>>(p_x, XDIM, W_ih, G4, p_part, B, G4, 336);
        // fused gates-reduce + LSTM cell + masked carry update
        k_lstm<<<(B*D)/256, 256>>>(b_ih, t);
        // preds = hnew @ W_fc  (N=10000, K=512, S=2, Kc=256)
        k_gemm128<<<dim3((V + GBN - 1)/GBN, 1, 2), 256>>>(p_hnew, D, W_fc, V, p_part, B, V, 256);
        k_epi_preds<<<(B*V + 255)/256, 256>>>(b_fc, out, t);
    }
}

// round 3
// speedup vs baseline: 2.1392x; 1.1710x over previous
#include <cuda_runtime.h>
#include <math.h>
#include <stdint.h>

// Problem constants
#define B   128
#define P   196
#define E   2048
#define AA  512
#define EMB 512
#define D   512
#define V   10000
#define LCD 128
#define TCAP 26
#define T   25
#define XDIM (EMB + E + LCD)   // 2688
#define G4  (4*D)              // 2048
#define NCAT (AA + E + G4)     // 4608

// Output layout: predictions (B,T,V), caps (B,TCAP), dec_len (B,), alphas (B,T,P), sort_ind (B,)
#define OFF_PRED   ((size_t)0)
#define OFF_CAPS   ((size_t)B*T*V)
#define OFF_DECLEN (OFF_CAPS + (size_t)B*TCAP)
#define OFF_ALPHAS (OFF_DECLEN + (size_t)B)
#define OFF_SORT   (OFF_ALPHAS + (size_t)B*T*P)

// ------------------- scratch -------------------
__device__ float g_att1[(size_t)B*P*AA];   // sorted-order enc @ W_enc_att (no bias)
__device__ float g_Wcat[(size_t)D*NCAT];   // [W_dec_att | W_fbeta | W_hh]
__device__ float g_part[2560000];          // split-K partials
__device__ float g_mean[B*E];
__device__ float g_h[B*D];
__device__ float g_c[B*D];
__device__ float g_hnew[B*D];
__device__ float g_att2[B*AA];             // + b_dec + b_enc folded
__device__ float g_alpha[B*P];
__device__ float g_gate[B*E];              // sigmoided
__device__ float g_hh[B*G4];               // h @ W_hh + b_hh
__device__ float g_x[B*XDIM];
__device__ int   g_sort[B];
__device__ int   g_declen[B];
__device__ float g_maskf[B];

// ------------------- sort + small outputs + style into x -------------------
__global__ void k_sort(const int* __restrict__ caps_in,
                       const int* __restrict__ cap_len,
                       const int* __restrict__ length_class,
                       const float* __restrict__ lc_table,
                       float* __restrict__ out)
{
    __shared__ int cls[B];
    int i = threadIdx.x;
    cls[i] = cap_len[i];
    __syncthreads();
    int my = cls[i];
    int rank = 0;
    for (int j = 0; j < B; j++) {
        int cj = cls[j];
        if (cj > my || (cj == my && j < i)) rank++;
    }
    g_sort[rank] = i;
    __syncthreads();
    int si = g_sort[i];
    int dl = cls[si] - 1;
    g_declen[i] = dl;
    out[OFF_DECLEN + i] = (float)dl;
    out[OFF_SORT + i]   = (float)si;
    for (int tt = 0; tt < TCAP; tt++)
        out[OFF_CAPS + (size_t)i*TCAP + tt] = (float)caps_in[si*TCAP + tt];
    int lcidx = length_class[si];
    for (int j = 0; j < LCD; j++)
        g_x[(size_t)i*XDIM + EMB + j] = lc_table[lcidx*LCD + j];  // style, constant over t
}

// ------------------- mean over pixels (indirect) -------------------
__global__ void k_mean(const float* __restrict__ enc)
{
    int b = blockIdx.y;
    int e = blockIdx.x * 256 + threadIdx.x;
    const float* base = enc + (size_t)g_sort[b]*P*E + e;
    float s = 0.f;
    #pragma unroll 4
    for (int p = 0; p < P; p++) s += base[(size_t)p*E];
    g_mean[b*E + e] = s * (1.0f / (float)P);
}

// ------------------- concat weights -------------------
__global__ void k_concatW(const float* __restrict__ Wdec,
                          const float* __restrict__ Wfb,
                          const float* __restrict__ Whh)
{
    int idx = blockIdx.x * 256 + threadIdx.x;
    if (idx >= D * NCAT) return;
    int k = idx / NCAT, n = idx % NCAT;
    float v;
    if (n < AA)            v = Wdec[k*AA + n];
    else if (n < AA + E)   v = Wfb[k*E + (n - AA)];
    else                   v = Whh[k*G4 + (n - AA - E)];
    g_Wcat[idx] = v;
}

// =================== fp32 SIMT GEMM (recurrent path), split-K partials ===================
#define GBM 128
#define GBN 64
#define GBK 16

__global__ __launch_bounds__(256)
void k_gemm128(const float* __restrict__ Am, int lda,
               const float* __restrict__ W,  int ldw,
               float* __restrict__ part,
               int M, int N, int Kc)
{
    __shared__ float As[2][GBK][GBM];
    __shared__ float Ws[2][GBK][GBN];
    int tid = threadIdx.x;
    int bn = blockIdx.x * GBN;
    int bm = blockIdx.y * GBM;
    int kbase = blockIdx.z * Kc;

    int a_m = tid >> 1;
    int a_k = (tid & 1) * 8;
    int w_k = tid >> 4;
    int w_n = (tid & 15) * 4;
    int tx = tid & 15, ty = tid >> 4;
    int ty8 = ty * 8, tx4 = tx * 4;

    const float* arow = Am + (size_t)(bm + a_m) * lda + kbase + a_k;
    const float* wptr = W + (size_t)(kbase + w_k) * ldw + bn + w_n;
    bool wok = (bn + w_n) < N;

    float acc[8][4];
    #pragma unroll
    for (int i = 0; i < 8; i++)
        #pragma unroll
        for (int j = 0; j < 4; j++) acc[i][j] = 0.f;

    int iters = Kc / GBK;
    {
        float4 a0 = *(const float4*)(arow);
        float4 a1 = *(const float4*)(arow + 4);
        float4 w  = wok ? *(const float4*)(wptr) : make_float4(0,0,0,0);
        As[0][a_k+0][a_m] = a0.x; As[0][a_k+1][a_m] = a0.y;
        As[0][a_k+2][a_m] = a0.z; As[0][a_k+3][a_m] = a0.w;
        As[0][a_k+4][a_m] = a1.x; As[0][a_k+5][a_m] = a1.y;
        As[0][a_k+6][a_m] = a1.z; As[0][a_k+7][a_m] = a1.w;
        *(float4*)&Ws[0][w_k][w_n] = w;
    }
    __syncthreads();

    int buf = 0;
    for (int it = 0; it < iters; it++) {
        float4 pa0, pa1, pw;
        bool has_next = (it + 1 < iters);
        if (has_next) {
            const float* an = arow + (it + 1) * GBK;
            pa0 = *(const float4*)(an);
            pa1 = *(const float4*)(an + 4);
            pw  = wok ? *(const float4*)(wptr + (size_t)(it + 1) * GBK * ldw)
                      : make_float4(0,0,0,0);
        }
        #pragma unroll
        for (int kk = 0; kk < GBK; kk++) {
            float4 a0 = *(const float4*)&As[buf][kk][ty8];
            float4 a1 = *(const float4*)&As[buf][kk][ty8 + 4];
            float4 w  = *(const float4*)&Ws[buf][kk][tx4];
            float av[8] = {a0.x,a0.y,a0.z,a0.w,a1.x,a1.y,a1.z,a1.w};
            float wv[4] = {w.x,w.y,w.z,w.w};
            #pragma unroll
            for (int i = 0; i < 8; i++)
                #pragma unroll
                for (int j = 0; j < 4; j++)
                    acc[i][j] += av[i] * wv[j];
        }
        if (has_next) {
            int nb = buf ^ 1;
            As[nb][a_k+0][a_m] = pa0.x; As[nb][a_k+1][a_m] = pa0.y;
            As[nb][a_k+2][a_m] = pa0.z; As[nb][a_k+3][a_m] = pa0.w;
            As[nb][a_k+4][a_m] = pa1.x; As[nb][a_k+5][a_m] = pa1.y;
            As[nb][a_k+6][a_m] = pa1.z; As[nb][a_k+7][a_m] = pa1.w;
            *(float4*)&Ws[nb][w_k][w_n] = pw;
        }
        __syncthreads();
        buf ^= 1;
    }

    float* pout = part + (size_t)blockIdx.z * M * N;
    #pragma unroll
    for (int i = 0; i < 8; i++) {
        int gm = bm + ty8 + i;
        #pragma unroll
        for (int j = 0; j < 4; j++) {
            int gn = bn + tx4 + j;
            if (gn < N) pout[(size_t)gm * N + gn] = acc[i][j];
        }
    }
}

// =================== TF32 tensor-core GEMM (mma.sync m16n8k8) ===================
// C_part[z] = A[rows remapped][kbase..] @ W[kbase..][bn..]
#define MM_BM 128
#define MM_BN 64
#define MM_BK 16
#define MM_PAD 4

__device__ __forceinline__ uint32_t f2tf32(float x) {
    uint32_t u;
    asm("cvt.rna.tf32.f32 %0, %1;" : "=r"(u) : "f"(x));
    return u;
}
__device__ __forceinline__ void mma_tf32(float* c, const uint32_t* a, const uint32_t* b) {
    asm volatile("mma.sync.aligned.m16n8k8.row.col.f32.tf32.tf32.f32 "
                 "{%0,%1,%2,%3}, {%4,%5,%6,%7}, {%8,%9}, {%0,%1,%2,%3};"
                 : "+f"(c[0]), "+f"(c[1]), "+f"(c[2]), "+f"(c[3])
                 : "r"(a[0]), "r"(a[1]), "r"(a[2]), "r"(a[3]),
                   "r"(b[0]), "r"(b[1]));
}

__global__ __launch_bounds__(256)
void k_mma(const float* __restrict__ Am, int lda,
           const float* __restrict__ W,  int ldw,
           float* __restrict__ Cout,
           int M, int N, int Kc,
           const int* __restrict__ rowmap, int rowdiv)
{
    __shared__ uint32_t As[MM_BM][MM_BK + MM_PAD];   // [m][k]
    __shared__ uint32_t Ws[MM_BN][MM_BK + MM_PAD];   // [n][k]
    int tid = threadIdx.x;
    int lane = tid & 31, wid = tid >> 5;
    int wm = wid & 1, wn = wid >> 1;                 // 2 x 4 warps
    int bn = blockIdx.x * MM_BN;
    int bm = blockIdx.y * MM_BM;
    int kbase = blockIdx.z * Kc;

    // A loader
    int a_m = tid >> 1, a_k = (tid & 1) * 8;
    int gm = bm + a_m;
    int arow = gm;
    if (rowmap) { int bb = gm / rowdiv; int pp = gm - bb * rowdiv; arow = rowmap[bb] * rowdiv + pp; }
    const float* aptr = Am + (size_t)arow * lda + kbase + a_k;
    // W loader (transposing)
    int w_k = tid >> 4, w_n = (tid & 15) * 4;
    const float* wptr = W + (size_t)(kbase + w_k) * ldw + bn + w_n;
    bool wok = (bn + w_n) < N;

    float c[4][2][4];
    #pragma unroll
    for (int i = 0; i < 4; i++)
        #pragma unroll
        for (int j = 0; j < 2; j++)
            #pragma unroll
            for (int q = 0; q < 4; q++) c[i][j][q] = 0.f;

    int iters = Kc / MM_BK;
    float4 pa0 = *(const float4*)(aptr);
    float4 pa1 = *(const float4*)(aptr + 4);
    float4 pw  = wok ? *(const float4*)(wptr) : make_float4(0,0,0,0);

    for (int it = 0; it < iters; it++) {
        // store current regs to smem (tf32-converted)
        {
            uint4 v0 = make_uint4(f2tf32(pa0.x), f2tf32(pa0.y), f2tf32(pa0.z), f2tf32(pa0.w));
            uint4 v1 = make_uint4(f2tf32(pa1.x), f2tf32(pa1.y), f2tf32(pa1.z), f2tf32(pa1.w));
            *(uint4*)&As[a_m][a_k]     = v0;
            *(uint4*)&As[a_m][a_k + 4] = v1;
            Ws[w_n+0][w_k] = f2tf32(pw.x);
            Ws[w_n+1][w_k] = f2tf32(pw.y);
            Ws[w_n+2][w_k] = f2tf32(pw.z);
            Ws[w_n+3][w_k] = f2tf32(pw.w);
        }
        __syncthreads();
        if (it + 1 < iters) {
            const float* an = aptr + (it + 1) * MM_BK;
            pa0 = *(const float4*)(an);
            pa1 = *(const float4*)(an + 4);
            pw  = wok ? *(const float4*)(wptr + (size_t)(it + 1) * MM_BK * ldw)
                      : make_float4(0,0,0,0);
        }
        // compute 2 k-steps of 8
        #pragma unroll
        for (int ks = 0; ks < 2; ks++) {
            int krow = ks * 8 + (lane & 3);
            uint32_t afr[4][4], bfr[2][2];
            #pragma unroll
            for (int i = 0; i < 4; i++) {
                int r = wm * 64 + i * 16 + (lane >> 2);
                afr[i][0] = As[r][krow];
                afr[i][1] = As[r + 8][krow];
                afr[i][2] = As[r][krow + 4];
                afr[i][3] = As[r + 8][krow + 4];
            }
            #pragma unroll
            for (int j = 0; j < 2; j++) {
                int cc = wn * 16 + j * 8 + (lane >> 2);
                bfr[j][0] = Ws[cc][krow];
                bfr[j][1] = Ws[cc][krow + 4];
            }
            #pragma unroll
            for (int i = 0; i < 4; i++)
                #pragma unroll
                for (int j = 0; j < 2; j++)
                    mma_tf32(c[i][j], afr[i], bfr[j]);
        }
        __syncthreads();
    }

    float* pout = Cout + (size_t)blockIdx.z * M * N;
    #pragma unroll
    for (int i = 0; i < 4; i++) {
        int r0 = bm + wm * 64 + i * 16 + (lane >> 2);
        #pragma unroll
        for (int j = 0; j < 2; j++) {
            int cc = bn + wn * 16 + j * 8 + (lane & 3) * 2;
            if (cc < N) {
                *(float2*)&pout[(size_t)r0 * N + cc]       = make_float2(c[i][j][0], c[i][j][1]);
                *(float2*)&pout[(size_t)(r0+8) * N + cc]   = make_float2(c[i][j][2], c[i][j][3]);
            }
        }
    }
}

// ------------------- epilogue: fused h-GEMM (S=4) -------------------
__global__ void k_epi_h(const float* __restrict__ b_dec, const float* __restrict__ b_enc,
                        const float* __restrict__ b_fbeta, const float* __restrict__ b_hh)
{
    int idx = blockIdx.x * 256 + threadIdx.x;
    if (idx >= B * NCAT) return;
    int b = idx / NCAT, n = idx % NCAT;
    float s = g_part[idx] + g_part[(size_t)1*B*NCAT + idx]
            + g_part[(size_t)2*B*NCAT + idx] + g_part[(size_t)3*B*NCAT + idx];
    if (n < AA) {
        g_att2[b*AA + n] = s + b_dec[n] + b_enc[n];
    } else if (n < AA + E) {
        int j = n - AA;
        g_gate[b*E + j] = 1.f / (1.f + expf(-(s + b_fbeta[j])));
    } else {
        int j = n - AA - E;
        g_hh[b*G4 + j] = s + b_hh[j];
    }
}

// ------------------- epilogue: init h / c (S=8, N=512) -------------------
__global__ void k_epi_hc(float* __restrict__ dst, const float* __restrict__ bias)
{
    int idx = blockIdx.x * 256 + threadIdx.x;
    int n = idx % D;
    float s = bias[n];
    #pragma unroll
    for (int z = 0; z < 8; z++) s += g_part[(size_t)z*B*D + idx];
    dst[idx] = s;
}

// ------------------- attention scores + softmax + emb slice of x -------------------
__global__ void k_escore(const float* __restrict__ w_full,
                         const float* __restrict__ b_full,
                         const float* __restrict__ emb_table,
                         const int* __restrict__ caps_in,
                         float* __restrict__ out, int t)
{
    int b = blockIdx.x;
    __shared__ float att2s[AA], ws[AA], es[P], red[256];
    int tid = threadIdx.x;
    for (int j = tid; j < AA; j += 256) {
        att2s[j] = g_att2[b*AA + j];
        ws[j]    = w_full[j];
    }
    __syncthreads();
    int warp = tid >> 5, lane = tid & 31;
    float bf = *b_full;
    for (int p = warp; p < P; p += 8) {
        const float* row = g_att1 + ((size_t)b*P + p)*AA;
        float acc = 0.f;
        #pragma unroll 4
        for (int a = lane; a < AA; a += 32) {
            float v = row[a] + att2s[a];
            v = fmaxf(v, 0.f);
            acc += v * ws[a];
        }
        #pragma unroll
        for (int o = 16; o > 0; o >>= 1) acc += __shfl_down_sync(0xffffffffu, acc, o);
        if (lane == 0) es[p] = acc + bf;
    }
    __syncthreads();
    float m = -1e30f;
    for (int p = tid; p < P; p += 256) m = fmaxf(m, es[p]);
    red[tid] = m; __syncthreads();
    for (int s = 128; s > 0; s >>= 1) { if (tid < s) red[tid] = fmaxf(red[tid], red[tid+s]); __syncthreads(); }
    float mx = red[0]; __syncthreads();
    float sum = 0.f;
    for (int p = tid; p < P; p += 256) sum += expf(es[p] - mx);
    red[tid] = sum; __syncthreads();
    for (int s = 128; s > 0; s >>= 1) { if (tid < s) red[tid] += red[tid+s]; __syncthreads(); }
    float inv = 1.f / red[0];
    float maskv = (t < g_declen[b]) ? 1.f : 0.f;
    if (tid == 0) g_maskf[b] = maskv;
    for (int p = tid; p < P; p += 256) {
        float al = expf(es[p] - mx) * inv;
        g_alpha[b*P + p] = al;
        out[OFF_ALPHAS + ((size_t)b*T + t)*P + p] = al * maskv;
    }
    // emb slice of x for this step
    int cap = caps_in[g_sort[b]*TCAP + t];
    if (tid < EMB/4) {
        const float4* esrc = (const float4*)(emb_table + (size_t)cap*EMB);
        float4* edst = (float4*)(g_x + (size_t)b*XDIM);
        edst[tid] = esrc[tid];
    }
}

// ------------------- awe: alpha-weighted enc, writes gate*awe into x -------------------
__global__ void k_awe(const float* __restrict__ enc)
{
    int b  = blockIdx.y;
    int e0 = blockIdx.x * 512;
    __shared__ float als[P];
    int tid = threadIdx.x;
    if (tid < P) als[tid] = g_alpha[b*P + tid];
    __syncthreads();
    float acc0 = 0.f, acc1 = 0.f;
    const float* base = enc + (size_t)g_sort[b]*P*E + e0 + tid;
    #pragma unroll 2
    for (int p = 0; p < P; p++) {
        float al = als[p];
        acc0 += base[(size_t)p*E]       * al;
        acc1 += base[(size_t)p*E + 256] * al;
    }
    int j0 = e0 + tid;
    g_x[(size_t)b*XDIM + EMB + LCD + j0]       = g_gate[b*E + j0]       * acc0;
    g_x[(size_t)b*XDIM + EMB + LCD + j0 + 256] = g_gate[b*E + j0 + 256] * acc1;
}

// ------------------- fused W_ih epilogue + LSTM pointwise (S=8) -------------------
__global__ void k_lstm(const float* __restrict__ b_ih, int t)
{
    int idx = blockIdx.x * 256 + threadIdx.x;
    int b = idx / D, j = idx % D;
    float gate4[4];
    #pragma unroll
    for (int g = 0; g < 4; g++) {
        int n = g * D + j;
        float s = b_ih[n] + g_hh[b*G4 + n];
        #pragma unroll
        for (int z = 0; z < 8; z++)
            s += g_part[(size_t)z*B*G4 + (size_t)b*G4 + n];
        gate4[g] = s;
    }
    float si = 1.f / (1.f + expf(-gate4[0]));
    float sf = 1.f / (1.f + expf(-gate4[1]));
    float so = 1.f / (1.f + expf(-gate4[3]));
    float cn = sf * g_c[idx] + si * tanhf(gate4[2]);
    float hn = so * tanhf(cn);
    g_hnew[idx] = hn;
    if (t < g_declen[b]) { g_h[idx] = hn; g_c[idx] = cn; }
}

// ------------------- preds epilogue (S=2) -------------------
__global__ void k_epi_preds(const float* __restrict__ b_fc,
                            float* __restrict__ out, int t)
{
    int idx = blockIdx.x * 256 + threadIdx.x;
    if (idx >= B * V) return;
    int b = idx / V, n = idx % V;
    float s = g_part[idx] + g_part[(size_t)B*V + idx] + b_fc[n];
    out[OFF_PRED + (size_t)b*T*V + (size_t)t*V + n] = s * g_maskf[b];
}

// ------------------- host launcher -------------------
extern "C" void kernel_launch(void* const* d_in, const int* in_sizes, int n_in,
                              void* d_out, int out_size)
{
    const float* encoder_out  = (const float*)d_in[0];
    const int*   caps_in      = (const int*)  d_in[1];
    const int*   cap_len      = (const int*)  d_in[2];
    const int*   length_class = (const int*)  d_in[3];
    const float* W_enc_att    = (const float*)d_in[4];
    const float* b_enc_att    = (const float*)d_in[5];
    const float* W_dec_att    = (const float*)d_in[6];
    const float* b_dec_att    = (const float*)d_in[7];
    const float* w_full_att   = (const float*)d_in[8];
    const float* b_full_att   = (const float*)d_in[9];
    const float* W_init_h     = (const float*)d_in[10];
    const float* b_init_h     = (const float*)d_in[11];
    const float* W_init_c     = (const float*)d_in[12];
    const float* b_init_c     = (const float*)d_in[13];
    const float* W_fbeta      = (const float*)d_in[14];
    const float* b_fbeta      = (const float*)d_in[15];
    const float* emb_table    = (const float*)d_in[16];
    const float* lc_table     = (const float*)d_in[17];
    const float* W_fc         = (const float*)d_in[18];
    const float* b_fc         = (const float*)d_in[19];
    const float* W_ih         = (const float*)d_in[20];
    const float* b_ih         = (const float*)d_in[21];
    const float* W_hh         = (const float*)d_in[22];
    const float* b_hh         = (const float*)d_in[23];
    float* out = (float*)d_out;

    void* tmp;
    float *p_att1, *p_mean, *p_h, *p_c, *p_hnew, *p_x, *p_Wcat, *p_part;
    int* p_sort;
    cudaGetSymbolAddress(&tmp, g_att1);  p_att1 = (float*)tmp;
    cudaGetSymbolAddress(&tmp, g_mean);  p_mean = (float*)tmp;
    cudaGetSymbolAddress(&tmp, g_h);     p_h    = (float*)tmp;
    cudaGetSymbolAddress(&tmp, g_c);     p_c    = (float*)tmp;
    cudaGetSymbolAddress(&tmp, g_hnew);  p_hnew = (float*)tmp;
    cudaGetSymbolAddress(&tmp, g_x);     p_x    = (float*)tmp;
    cudaGetSymbolAddress(&tmp, g_Wcat);  p_Wcat = (float*)tmp;
    cudaGetSymbolAddress(&tmp, g_part);  p_part = (float*)tmp;
    cudaGetSymbolAddress(&tmp, g_sort);  p_sort = (int*)tmp;

    // ---- setup ----
    k_sort<<<1, B>>>(caps_in, cap_len, length_class, lc_table, out);
    k_concatW<<<(D*NCAT + 255)/256, 256>>>(W_dec_att, W_fbeta, W_hh);
    k_mean<<<dim3(E/256, B), 256>>>(encoder_out);

    // h0 / c0 (fp32, S=8)
    k_gemm128<<<dim3(D/GBN, 1, 8), 256>>>(p_mean, E, W_init_h, D, p_part, B, D, 256);
    k_epi_hc<<<(B*D)/256, 256>>>(p_h, b_init_h);
    k_gemm128<<<dim3(D/GBN, 1, 8), 256>>>(p_mean, E, W_init_c, D, p_part, B, D, 256);
    k_epi_hc<<<(B*D)/256, 256>>>(p_c, b_init_c);

    // att1 = enc[sort] @ W_enc_att  — TF32 tensor cores, row-remapped A, direct write
    k_mma<<<dim3(AA/MM_BN, (B*P)/MM_BM, 1), 256>>>(encoder_out, E, W_enc_att, AA,
                                                   p_att1, B*P, AA, E, p_sort, P);

    for (int t = 0; t < T; t++) {
        // fused: h @ [W_dec|W_fbeta|W_hh]  (fp32, S=4)
        k_gemm128<<<dim3(NCAT/GBN, 1, 4), 256>>>(p_h, D, p_Wcat, NCAT, p_part, B, NCAT, 128);
        k_epi_h<<<(B*NCAT + 255)/256, 256>>>(b_dec_att, b_enc_att, b_fbeta, b_hh);
        // scores + softmax + emb slice of x
        k_escore<<<B, 256>>>(w_full_att, b_full_att, emb_table, caps_in, out, t);
        // awe (writes gate*awe into x)
        k_awe<<<dim3(E/512, B), 256>>>(encoder_out);
        // x @ W_ih  (fp32, S=8)
        k_gemm128<<<dim3(G4/GBN, 1, 8), 256>>>(p_x, XDIM, W_ih, G4, p_part, B, G4, 336);
        k_lstm<<<(B*D)/256, 256>>>(b_ih, t);
        // preds = hnew @ W_fc  — TF32 tensor cores, S=2
        k_mma<<<dim3((V + MM_BN - 1)/MM_BN, 1, 2), 256>>>(p_hnew, D, W_fc, V,
                                                          p_part, B, V, 256, nullptr, 0);
        k_epi_preds<<<(B*V + 255)/256, 256>>>(b_fc, out, t);
    }
}